// round 7
// baseline (speedup 1.0000x reference)
#include <cuda_runtime.h>
#include <cuda_bf16.h>
#include <cstdint>

#define C_DIM 256
#define K_DIM 1024
#define HW    1024
#define N_TOK (64 * HW)
#define EPS_GAP 2e-4f
#define FLT_BIG 3.4e38f

// ---------------- device globals (scratch; no runtime allocation) ----------------
__device__ __align__(16) __nv_bfloat16 g_ehi[K_DIM * C_DIM];   // bf16 hi of emb [k][c]
__device__ __align__(16) __nv_bfloat16 g_elo[K_DIM * C_DIM];   // bf16 lo residual
__device__ __align__(16) __nv_bfloat16 g_zhi[N_TOK * C_DIM];   // bf16 hi of z [n][c]
__device__ __align__(16) __nv_bfloat16 g_zlo[N_TOK * C_DIM];   // bf16 lo residual
__device__ __align__(16) float g_esq[K_DIM];
__device__ __align__(16) float g_zsq[N_TOK];
__device__ int    g_ind[N_TOK];
__device__ int    g_flag[N_TOK];
__device__ double g_sumsq;
__device__ double g_sumlin;

// ---------------- helpers ----------------
__device__ __forceinline__ uint32_t smem_to_u32(const void* p) {
    uint32_t a;
    asm("{ .reg .u64 t; cvta.to.shared.u64 t, %1; cvt.u32.u64 %0, t; }" : "=r"(a) : "l"(p));
    return a;
}
__device__ __forceinline__ void cp_async16(uint32_t dst, const void* src) {
    asm volatile("cp.async.ca.shared.global [%0], [%1], 16;" :: "r"(dst), "l"(src) : "memory");
}
__device__ __forceinline__ void ldsm_x4(uint32_t* r, uint32_t addr) {
    asm volatile("ldmatrix.sync.aligned.m8n8.x4.shared.b16 {%0,%1,%2,%3}, [%4];"
                 : "=r"(r[0]), "=r"(r[1]), "=r"(r[2]), "=r"(r[3]) : "r"(addr));
}
__device__ __forceinline__ void mma_bf16(float* c, const uint32_t* a, uint32_t b0, uint32_t b1) {
    asm volatile("mma.sync.aligned.m16n8k16.row.col.f32.bf16.bf16.f32 "
                 "{%0,%1,%2,%3}, {%4,%5,%6,%7}, {%8,%9}, {%0,%1,%2,%3};"
                 : "+f"(c[0]), "+f"(c[1]), "+f"(c[2]), "+f"(c[3])
                 : "r"(a[0]), "r"(a[1]), "r"(a[2]), "r"(a[3]), "r"(b0), "r"(b1));
}
// Emulate reference fp32 chain: d = fl( fl(zsq + esq) - fl(2*ez) )
__device__ __forceinline__ float ref_dist(float zsq, float esq, float ez) {
    float t = __fadd_rn(zsq, esq);
    return __fadd_rn(t, __fmul_rn(-2.0f, ez));
}

// ---------------- prep kernels ----------------
__global__ void vq_zero_kernel() { g_sumsq = 0.0; g_sumlin = 0.0; }

__global__ void vq_esplit_kernel(const float* __restrict__ emb) {
    int idx = blockIdx.x * 256 + threadIdx.x;     // 262144 elems
    float x = emb[idx];
    __nv_bfloat16 hi = __float2bfloat16_rn(x);
    g_ehi[idx] = hi;
    g_elo[idx] = __float2bfloat16_rn(__fsub_rn(x, __bfloat162float(hi)));
}

// z [b][c][s] -> zhi/zlo [n][c] bf16 (tiled transpose + split)
__global__ void vq_zsplit_kernel(const float* __restrict__ z) {
    __shared__ float t[32][33];
    int b = blockIdx.z, c0 = blockIdx.y * 32, s0 = blockIdx.x * 32;
    int tx = threadIdx.x, ty = threadIdx.y;
#pragma unroll
    for (int r = ty; r < 32; r += 8)
        t[r][tx] = z[((size_t)(b * C_DIM + c0 + r)) * HW + s0 + tx];
    __syncthreads();
#pragma unroll
    for (int r = ty; r < 32; r += 8) {
        float x = t[tx][r];
        __nv_bfloat16 hi = __float2bfloat16_rn(x);
        size_t o = ((size_t)(b * HW + s0 + r)) * C_DIM + c0 + tx;
        g_zhi[o] = hi;
        g_zlo[o] = __float2bfloat16_rn(__fsub_rn(x, __bfloat162float(hi)));
    }
}

// ||e_k||^2: STRICT sequential fp32, mul/add separately rounded
__global__ void vq_esq_kernel(const float* __restrict__ emb) {
    int k = blockIdx.x * blockDim.x + threadIdx.x;
    if (k >= K_DIM) return;
    const float* row = emb + (size_t)k * C_DIM;
    float acc = 0.0f;
    for (int c = 0; c < C_DIM; c++) {
        float v = row[c];
        acc = __fadd_rn(acc, __fmul_rn(v, v));
    }
    g_esq[k] = acc;
}

// ||z_n||^2: STRICT sequential fp32 over c ascending
__global__ void vq_zsq_kernel(const float* __restrict__ z) {
    int n = blockIdx.x * blockDim.x + threadIdx.x;
    int b = n >> 10, s = n & (HW - 1);
    const float* base = z + ((size_t)b * C_DIM) * HW + s;
    float acc = 0.0f;
    for (int c = 0; c < C_DIM; c++) {
        float v = base[(size_t)c * HW];
        acc = __fadd_rn(acc, __fmul_rn(v, v));
    }
    g_zsq[n] = acc;
}

// ---------------- main mma.sync kernel ----------------
// CTA: 128 tokens x 1024 codes; 512 thr = 16 warps (4m x 4n), warp tile 32x64.
// K staged in chunks of 32 bf16, double-buffered via cp.async.
// smem row stride 40 bf16 (80B) -> conflict-free ldmatrix.
#define STRIDE   40
#define Z_TILE_B (128 * STRIDE * 2)          // 10240
#define E_TILE_B (256 * STRIDE * 2)          // 20480
#define BUF_B    (2 * Z_TILE_B + 2 * E_TILE_B)  // 61440
#define OFF_ZLO  Z_TILE_B
#define OFF_EHI  (2 * Z_TILE_B)
#define OFF_ELO  (2 * Z_TILE_B + E_TILE_B)
#define OFF_ESQ  (2 * BUF_B)                 // 122880, 1024 floats
#define OFF_MM1  (OFF_ESQ + 4096)            // 512 floats
#define OFF_MM2  (OFF_MM1 + 2048)            // 512 floats
#define OFF_MK1  (OFF_MM2 + 2048)            // 512 ints
#define SMEM_MMA_BYTES (OFF_MK1 + 2048)      // 133120

__global__ __launch_bounds__(512, 1)
void vq_mma_kernel() {
    extern __shared__ char smem[];
    const uint32_t sb = smem_to_u32(smem);
    float* esq_s = (float*)(smem + OFF_ESQ);
    float* mm1 = (float*)(smem + OFF_MM1);
    float* mm2 = (float*)(smem + OFF_MM2);
    int*   mk1 = (int*)(smem + OFF_MK1);

    const int tid = threadIdx.x, lane = tid & 31, warp = tid >> 5;
    const int wm = warp & 3, wn = warp >> 2;            // 4 x 4 warp grid
    const int tok0 = blockIdx.x * 128;

    // esq -> smem
    esq_s[tid] = g_esq[tid];
    esq_s[tid + 512] = g_esq[tid + 512];

    // rows owned by this thread (c-frag layout): wm*32 + tm*16 + h*8 + lane/4
    const int q = lane >> 2;
    float zsq4[4], rm1[4], rm2[4];
    int rk1[4];
#pragma unroll
    for (int j = 0; j < 4; j++) {
        int row = wm * 32 + (j >> 1) * 16 + (j & 1) * 8 + q;
        zsq4[j] = g_zsq[tok0 + row];
        rm1[j] = FLT_BIG; rm2[j] = FLT_BIG; rk1[j] = 1 << 30;
    }

    // ldmatrix address components
    const int g8 = lane >> 3, r8 = lane & 7;
    const int lrow = (g8 & 1) * 8 + r8;       // row within 16
    const int lk   = (g8 >> 1) * 8;           // k offset within 16

    float acc[2][8][4];

    // stage-issue: stage s = ng*8 + kc ; writes buf s&1
    auto issue = [&](int s) {
        int ng = s >> 3, kc = s & 7;
        uint32_t bufb = sb + (uint32_t)(s & 1) * BUF_B;
        {   // Z: 128 rows x 4 segs of 8 bf16; one (row,seg) per thread, hi+lo
            int zr = tid >> 2, zs = tid & 3;
            size_t go = (size_t)(tok0 + zr) * C_DIM + kc * 32 + zs * 8;
            uint32_t so = (uint32_t)(zr * STRIDE + zs * 8) * 2;
            cp_async16(bufb + so, g_zhi + go);
            cp_async16(bufb + OFF_ZLO + so, g_zlo + go);
        }
#pragma unroll
        for (int rr = 0; rr < 2; rr++) {      // E: 256 rows x 4 segs, 2 per thread
            int idx = tid + rr * 512;
            int er = idx >> 2, es = idx & 3;
            size_t go = (size_t)(ng * 256 + er) * C_DIM + kc * 32 + es * 8;
            uint32_t so = (uint32_t)(er * STRIDE + es * 8) * 2;
            cp_async16(bufb + OFF_EHI + so, g_ehi + go);
            cp_async16(bufb + OFF_ELO + so, g_elo + go);
        }
    };

    issue(0);
    asm volatile("cp.async.commit_group;" ::: "memory");

    for (int s = 0; s < 32; s++) {
        const int ng = s >> 3, kc = s & 7;
        if (s + 1 < 32) {
            issue(s + 1);
            asm volatile("cp.async.commit_group;" ::: "memory");
            asm volatile("cp.async.wait_group 1;" ::: "memory");
        } else {
            asm volatile("cp.async.wait_group 0;" ::: "memory");
        }
        __syncthreads();

        if (kc == 0) {
#pragma unroll
            for (int tm = 0; tm < 2; tm++)
#pragma unroll
                for (int nf = 0; nf < 8; nf++)
#pragma unroll
                    for (int cc = 0; cc < 4; cc++) acc[tm][nf][cc] = 0.0f;
        }

        const uint32_t bufb = sb + (uint32_t)(s & 1) * BUF_B;
#pragma unroll
        for (int kk = 0; kk < 2; kk++) {
            const uint32_t kb = (uint32_t)(kk * 16 + lk) * 2;
            uint32_t ahi[2][4], alo[2][4];
#pragma unroll
            for (int tm = 0; tm < 2; tm++) {
                uint32_t ro = (uint32_t)((wm * 32 + tm * 16 + lrow) * STRIDE) * 2 + kb;
                ldsm_x4(ahi[tm], bufb + ro);
                ldsm_x4(alo[tm], bufb + OFF_ZLO + ro);
            }
#pragma unroll
            for (int p = 0; p < 4; p++) {     // 16 codes per p
                uint32_t bh[4], bl[4];
                uint32_t ro = (uint32_t)((wn * 64 + p * 16 + lrow) * STRIDE) * 2 + kb;
                ldsm_x4(bh, bufb + OFF_EHI + ro);
                ldsm_x4(bl, bufb + OFF_ELO + ro);
#pragma unroll
                for (int tm = 0; tm < 2; tm++) {
                    // codes p*16..+7 : frag {r0, r2};  +8..+15 : {r1, r3}
                    mma_bf16(acc[tm][2 * p],     ahi[tm], bh[0], bh[2]);
                    mma_bf16(acc[tm][2 * p],     ahi[tm], bl[0], bl[2]);
                    mma_bf16(acc[tm][2 * p],     alo[tm], bh[0], bh[2]);
                    mma_bf16(acc[tm][2 * p + 1], ahi[tm], bh[1], bh[3]);
                    mma_bf16(acc[tm][2 * p + 1], ahi[tm], bl[1], bl[3]);
                    mma_bf16(acc[tm][2 * p + 1], alo[tm], bh[1], bh[3]);
                }
            }
        }
        __syncthreads();   // buffer reuse guard

        if (kc == 7) {     // n-group epilogue: fold dists into running (m1,m2,k1)
            const int col0 = 2 * (lane & 3);
#pragma unroll
            for (int tm = 0; tm < 2; tm++)
#pragma unroll
                for (int h = 0; h < 2; h++) {
                    const int j = tm * 2 + h;
                    const float zs = zsq4[j];
#pragma unroll
                    for (int nf = 0; nf < 8; nf++) {
                        int kg = ng * 256 + wn * 64 + nf * 8 + col0;
#pragma unroll
                        for (int cc = 0; cc < 2; cc++) {
                            float d = ref_dist(zs, esq_s[kg + cc], acc[tm][nf][h * 2 + cc]);
                            int k = kg + cc;
                            if (d < rm1[j] || (d == rm1[j] && k < rk1[j])) {
                                rm2[j] = rm1[j]; rm1[j] = d; rk1[j] = k;
                            } else rm2[j] = fminf(rm2[j], d);
                        }
                    }
                }
        }
    }

    // quad merge (lanes sharing the same rows: xor 1, xor 2)
#pragma unroll
    for (int delta = 1; delta <= 2; delta <<= 1) {
#pragma unroll
        for (int j = 0; j < 4; j++) {
            float om1 = __shfl_xor_sync(0xffffffffu, rm1[j], delta);
            float om2 = __shfl_xor_sync(0xffffffffu, rm2[j], delta);
            int   ok1 = __shfl_xor_sync(0xffffffffu, rk1[j], delta);
            if (om1 < rm1[j] || (om1 == rm1[j] && ok1 < rk1[j])) {
                rm2[j] = fminf(om2, rm1[j]); rm1[j] = om1; rk1[j] = ok1;
            } else rm2[j] = fminf(rm2[j], om1);
        }
    }
    if ((lane & 3) == 0) {
#pragma unroll
        for (int j = 0; j < 4; j++) {
            int row = wm * 32 + (j >> 1) * 16 + (j & 1) * 8 + q;
            mm1[row * 4 + wn] = rm1[j];
            mm2[row * 4 + wn] = rm2[j];
            mk1[row * 4 + wn] = rk1[j];
        }
    }
    __syncthreads();
    if (tid < 128) {
        float m1 = mm1[tid * 4], m2 = mm2[tid * 4];
        int k1 = mk1[tid * 4];
#pragma unroll
        for (int w = 1; w < 4; w++) {
            float om1 = mm1[tid * 4 + w], om2 = mm2[tid * 4 + w];
            int ok1 = mk1[tid * 4 + w];
            if (om1 < m1 || (om1 == m1 && ok1 < k1)) {
                m2 = fminf(om2, m1); m1 = om1; k1 = ok1;
            } else m2 = fminf(m2, om1);
        }
        g_ind[tok0 + tid] = k1;
        g_flag[tok0 + tid] = (__fsub_rn(m2, m1) <= EPS_GAP) ? 1 : 0;
    }
}

// ---------------- exact pass: flagged tokens, full 1024-code exact argmin ----------------
__global__ __launch_bounds__(256)
void vq_exact_kernel(const float* __restrict__ z, const float* __restrict__ emb) {
    __shared__ float zv[8][C_DIM];
    const int wid = threadIdx.x >> 5, lane = threadIdx.x & 31;
    const int token = blockIdx.x * 8 + wid;
    if (g_flag[token] == 0) return;
    const int b = token >> 10, s = token & (HW - 1);
#pragma unroll
    for (int r = 0; r < 8; r++)
        zv[wid][lane + 32 * r] = z[((size_t)(b * C_DIM + lane + 32 * r)) * HW + s];
    __syncwarp();
    const float zsq = g_zsq[token];
    float bd = FLT_BIG;
    int bk = 1 << 30;
    for (int k = lane; k < K_DIM; k += 32) {
        const float* e = emb + (size_t)k * C_DIM;
        float acc = 0.0f;            // fused FMA, c ascending: matches ref bits
        for (int c = 0; c < C_DIM; c++)
            acc = __fmaf_rn(zv[wid][c], e[c], acc);
        float d = ref_dist(zsq, g_esq[k], acc);
        if (d < bd || (d == bd && k < bk)) { bd = d; bk = k; }
    }
#pragma unroll
    for (int m = 16; m > 0; m >>= 1) {
        float od = __shfl_xor_sync(0xffffffffu, bd, m);
        int   ok = __shfl_xor_sync(0xffffffffu, bk, m);
        if (od < bd || (od == bd && ok < bk)) { bd = od; bk = ok; }
    }
    if (lane == 0) g_ind[token] = bk;
}

// ---------------- output: gather z_q, NCHW write, loss ----------------
__global__ __launch_bounds__(256)
void vq_output_kernel(const float* __restrict__ z, const float* __restrict__ emb,
                      float* __restrict__ out) {
    __shared__ float s_red[16];
    const int tid = threadIdx.x;
    const int i = tid & 63, cg = tid >> 6;
    const int b = blockIdx.x >> 4, s0 = (blockIdx.x & 15) * 64;
    const int ind = g_ind[(b << 10) + s0 + i];
    const float* erow = emb + (size_t)ind * C_DIM;
    const float* zb = z + ((size_t)b * C_DIM) * HW + s0 + i;
    float* ob = out + ((size_t)b * C_DIM) * HW + s0 + i;
    float lsq = 0.0f, llin = 0.0f;
#pragma unroll 4
    for (int c2 = 0; c2 < 64; c2++) {
        int c = (c2 << 2) + cg;
        float qv = __ldg(erow + c);
        float zv = __ldg(zb + (size_t)c * HW);
        ob[(size_t)c * HW] = qv;
        float dff = qv - zv;
        lsq = fmaf(dff, dff, lsq);
        llin += dff;
    }
#pragma unroll
    for (int m = 16; m > 0; m >>= 1) {
        lsq  += __shfl_xor_sync(0xffffffffu, lsq, m);
        llin += __shfl_xor_sync(0xffffffffu, llin, m);
    }
    int wid = tid >> 5, lane = tid & 31;
    if (lane == 0) { s_red[wid] = lsq; s_red[8 + wid] = llin; }
    __syncthreads();
    if (tid == 0) {
        double a = 0.0, l = 0.0;
#pragma unroll
        for (int w = 0; w < 8; w++) { a += (double)s_red[w]; l += (double)s_red[8 + w]; }
        atomicAdd(&g_sumsq, a);
        atomicAdd(&g_sumlin, l);
    }
}

__global__ void vq_finalize_kernel(float* out, int nelem) {
    double m = (double)nelem;
    out[nelem] = (float)(g_sumsq / m + 0.25 * (g_sumlin / m));
}

// ---------------- launch ----------------
extern "C" void kernel_launch(void* const* d_in, const int* in_sizes, int n_in,
                              void* d_out, int out_size) {
    const float* z   = (const float*)d_in[0];   // [64,256,32,32]
    const float* emb = (const float*)d_in[1];   // [1024,256]
    float* out = (float*)d_out;                 // [64,256,32,32] ++ [loss]
    const int nelem = out_size - 1;             // 16777216

    cudaFuncSetAttribute(vq_mma_kernel,
                         cudaFuncAttributeMaxDynamicSharedMemorySize, (int)SMEM_MMA_BYTES);

    vq_zero_kernel<<<1, 1>>>();
    vq_esplit_kernel<<<K_DIM * C_DIM / 256, 256>>>(emb);
    vq_zsplit_kernel<<<dim3(HW / 32, C_DIM / 32, 64), dim3(32, 8)>>>(z);
    vq_esq_kernel<<<K_DIM / 256, 256>>>(emb);
    vq_zsq_kernel<<<N_TOK / 256, 256>>>(z);
    vq_mma_kernel<<<N_TOK / 128, 512, SMEM_MMA_BYTES>>>();
    vq_exact_kernel<<<N_TOK / 8, 256>>>(z, emb);
    vq_output_kernel<<<N_TOK / 64, 256>>>(z, emb, out);
    vq_finalize_kernel<<<1, 1>>>(out, nelem);
}